// round 1
// baseline (speedup 1.0000x reference)
#include <cuda_runtime.h>
#include <math.h>
#include <float.h>

// ---------------- problem constants ----------------
#define BB   2
#define NN   2048
#define DIM  1024
#define HH   16
#define DH   64
#define MEMS 16
#define ROT  32
#define JJ   (NN + MEMS)   // 2064
#define JP   2112          // padded to multiple of 64
#define PADR (JP - JJ)     // 48
#define QKSCALE 10.0f

#define SOFTMAX_SMEM (HH * JP * 4)   // 135168 bytes

// ---------------- device scratch ----------------
__device__ float g_rawq[BB * NN * DIM];
__device__ float g_rawk[BB * NN * DIM];
__device__ float g_rawv[BB * NN * DIM];
__device__ float g_q[BB * HH * NN * DH];
__device__ float g_k[BB * HH * JP * DH];
__device__ float g_v[BB * HH * JP * DH];
__device__ float g_dots[BB * HH * NN * JP];   // 553 MB
__device__ float g_o[BB * NN * DIM];

// ---------------- generic 64x64 tiled SGEMM (row-major), batched ----------------
// C = A(MxK) @ B(KxN). Requires M%64==0, N%64==0, K%16==0.
// cmode==1: C base per z = Cbase + (z/HH)*NN*DIM + (z%HH)*DH  (attention-output layout)
__global__ __launch_bounds__(256) void sgemm64(
    const float* __restrict__ A, const float* __restrict__ Bm, float* __restrict__ C,
    int M, int Nc, int K, int lda, int ldb, int ldc,
    long long sA, long long sB, long long sC, int cmode)
{
    __shared__ float As[16][68];
    __shared__ float Bs[16][64];

    const float* Ap = A + (long long)blockIdx.z * sA;
    const float* Bp = Bm + (long long)blockIdx.z * sB;
    float* Cp;
    if (cmode == 0) {
        Cp = C + (long long)blockIdx.z * sC;
    } else {
        int b = blockIdx.z / HH, g = blockIdx.z % HH;
        Cp = C + (long long)b * NN * DIM + g * DH;
    }

    int m0 = blockIdx.y * 64, n0 = blockIdx.x * 64;
    int tid = threadIdx.x;
    int tx = tid & 15, ty = tid >> 4;
    int arow = tid >> 2, acol = (tid & 3) << 2;   // A tile: 64 rows x 16 cols
    int brow = tid >> 4, bcol = (tid & 15) << 2;  // B tile: 16 rows x 64 cols

    float acc[4][4] = {};

    for (int k0 = 0; k0 < K; k0 += 16) {
        float4 a = *(const float4*)(Ap + (long long)(m0 + arow) * lda + k0 + acol);
        As[acol + 0][arow] = a.x;
        As[acol + 1][arow] = a.y;
        As[acol + 2][arow] = a.z;
        As[acol + 3][arow] = a.w;
        *(float4*)&Bs[brow][bcol] =
            *(const float4*)(Bp + (long long)(k0 + brow) * ldb + n0 + bcol);
        __syncthreads();
#pragma unroll
        for (int k = 0; k < 16; k++) {
            float4 ra = *(const float4*)&As[k][ty * 4];
            float4 rb = *(const float4*)&Bs[k][tx * 4];
            float av[4] = {ra.x, ra.y, ra.z, ra.w};
            float bv[4] = {rb.x, rb.y, rb.z, rb.w};
#pragma unroll
            for (int i = 0; i < 4; i++)
#pragma unroll
                for (int j = 0; j < 4; j++) acc[i][j] += av[i] * bv[j];
        }
        __syncthreads();
    }

#pragma unroll
    for (int i = 0; i < 4; i++)
#pragma unroll
        for (int j = 0; j < 4; j++)
            Cp[(long long)(m0 + ty * 4 + i) * ldc + n0 + tx * 4 + j] = acc[i][j];
}

// ---------------- l2norm + rotary for q, k, v ----------------
// one warp per (b, n, h) row of 64
__global__ __launch_bounds__(256) void normrot_kernel(const float* __restrict__ freqs)
{
    int gw = (blockIdx.x * blockDim.x + threadIdx.x) >> 5;
    int lane = threadIdx.x & 31;
    int h = gw % HH;
    int n = (gw / HH) % NN;
    int b = gw / (HH * NN);

    long long rbase = ((long long)(b * NN + n)) * DIM + h * DH;
    float f = freqs[n * ROT + lane];
    float cs = cosf(f), sn = sinf(f);

    // q: norm + rotary
    {
        float v0 = g_rawq[rbase + lane], v1 = g_rawq[rbase + 32 + lane];
        float ss = v0 * v0 + v1 * v1;
#pragma unroll
        for (int o = 16; o; o >>= 1) ss += __shfl_xor_sync(0xffffffffu, ss, o);
        float inv = 1.0f / fmaxf(sqrtf(ss), 1e-12f);
        v0 *= inv; v1 *= inv;
        float partner = __shfl_xor_sync(0xffffffffu, v0, 16);
        float rot = (lane < 16) ? -partner : partner;
        v0 = v0 * cs + rot * sn;
        long long ob = ((long long)((b * HH + h) * NN + n)) * DH;
        g_q[ob + lane] = v0;
        g_q[ob + 32 + lane] = v1;
    }
    // k: norm + rotary, stored at row MEM+n
    {
        float v0 = g_rawk[rbase + lane], v1 = g_rawk[rbase + 32 + lane];
        float ss = v0 * v0 + v1 * v1;
#pragma unroll
        for (int o = 16; o; o >>= 1) ss += __shfl_xor_sync(0xffffffffu, ss, o);
        float inv = 1.0f / fmaxf(sqrtf(ss), 1e-12f);
        v0 *= inv; v1 *= inv;
        float partner = __shfl_xor_sync(0xffffffffu, v0, 16);
        float rot = (lane < 16) ? -partner : partner;
        v0 = v0 * cs + rot * sn;
        long long ob = ((long long)((b * HH + h) * JP + (MEMS + n))) * DH;
        g_k[ob + lane] = v0;
        g_k[ob + 32 + lane] = v1;
    }
    // v: rotary only
    {
        float v0 = g_rawv[rbase + lane], v1 = g_rawv[rbase + 32 + lane];
        float partner = __shfl_xor_sync(0xffffffffu, v0, 16);
        float rot = (lane < 16) ? -partner : partner;
        v0 = v0 * cs + rot * sn;
        long long ob = ((long long)((b * HH + h) * JP + (MEMS + n))) * DH;
        g_v[ob + lane] = v0;
        g_v[ob + 32 + lane] = v1;
    }
}

// ---------------- memory slots (normalized mem_k, mem_v) + zero padding rows ----------------
// one warp per (b, h, r) where r in [0, MEMS+PADR)
__global__ __launch_bounds__(256) void memfill_kernel(
    const float* __restrict__ mem_k, const float* __restrict__ mem_v)
{
    int gw = (blockIdx.x * blockDim.x + threadIdx.x) >> 5;
    int lane = threadIdx.x & 31;
    const int RPW = MEMS + PADR;  // 64
    int r = gw % RPW;
    int h = (gw / RPW) % HH;
    int b = gw / (RPW * HH);

    if (r < MEMS) {
        long long ib = ((long long)(h * MEMS + r)) * DH;
        float k0 = mem_k[ib + lane], k1 = mem_k[ib + 32 + lane];
        float ss = k0 * k0 + k1 * k1;
#pragma unroll
        for (int o = 16; o; o >>= 1) ss += __shfl_xor_sync(0xffffffffu, ss, o);
        float inv = 1.0f / fmaxf(sqrtf(ss), 1e-12f);
        long long ob = ((long long)((b * HH + h) * JP + r)) * DH;
        g_k[ob + lane] = k0 * inv;
        g_k[ob + 32 + lane] = k1 * inv;
        g_v[ob + lane] = mem_v[ib + lane];
        g_v[ob + 32 + lane] = mem_v[ib + 32 + lane];
    } else {
        int rr = JJ + (r - MEMS);
        long long ob = ((long long)((b * HH + h) * JP + rr)) * DH;
        g_k[ob + lane] = 0.0f; g_k[ob + 32 + lane] = 0.0f;
        g_v[ob + lane] = 0.0f; g_v[ob + 32 + lane] = 0.0f;
    }
}

// ---------------- dots = QK_SCALE * Q @ K^T, batched over (b,h) ----------------
__global__ __launch_bounds__(256) void dots_kernel()
{
    __shared__ float Qs[64][68];
    __shared__ float Ks[64][68];

    int z = blockIdx.z;
    const float* Qp = g_q + (long long)z * NN * DH;
    const float* Kp = g_k + (long long)z * JP * DH;
    float* Dp = g_dots + (long long)z * NN * JP;

    int m0 = blockIdx.y * 64, j0 = blockIdx.x * 64;
    int tid = threadIdx.x;

#pragma unroll
    for (int it = 0; it < 4; it++) {
        int lin = tid + it * 256;
        int row = lin >> 4;
        int c4 = (lin & 15) << 2;
        float4 q = *(const float4*)(Qp + (long long)(m0 + row) * DH + c4);
        Qs[c4 + 0][row] = q.x; Qs[c4 + 1][row] = q.y;
        Qs[c4 + 2][row] = q.z; Qs[c4 + 3][row] = q.w;
        float4 k = *(const float4*)(Kp + (long long)(j0 + row) * DH + c4);
        Ks[c4 + 0][row] = k.x; Ks[c4 + 1][row] = k.y;
        Ks[c4 + 2][row] = k.z; Ks[c4 + 3][row] = k.w;
    }
    __syncthreads();

    int tx = tid & 15, ty = tid >> 4;
    float acc[4][4] = {};
#pragma unroll
    for (int d = 0; d < 64; d++) {
        float4 ra = *(const float4*)&Qs[d][ty * 4];
        float4 rb = *(const float4*)&Ks[d][tx * 4];
        float av[4] = {ra.x, ra.y, ra.z, ra.w};
        float bv[4] = {rb.x, rb.y, rb.z, rb.w};
#pragma unroll
        for (int i = 0; i < 4; i++)
#pragma unroll
            for (int j = 0; j < 4; j++) acc[i][j] += av[i] * bv[j];
    }

#pragma unroll
    for (int i = 0; i < 4; i++)
#pragma unroll
        for (int j = 0; j < 4; j++)
            Dp[(long long)(m0 + ty * 4 + i) * JP + j0 + tx * 4 + j] = acc[i][j] * QKSCALE;
}

// ---------------- th_pre mix -> mask -> softmax -> th_post mix (in place) ----------------
// one block per (b, i): 512 threads, warp g handles output head g
__global__ __launch_bounds__(512, 1) void mixsoftmax_kernel(
    const float* __restrict__ th_pre, const float* __restrict__ th_post)
{
    extern __shared__ float S[];           // [HH][JP]
    __shared__ float pre_s[HH * HH];
    __shared__ float post_s[HH * HH];

    int tid = threadIdx.x;
    int bi = blockIdx.x;
    int b = bi / NN, i = bi % NN;

    if (tid < 256) pre_s[tid] = th_pre[tid];
    else post_s[tid - 256] = th_post[tid - 256];

    const int JP4 = JP / 4;                // 528
    long long base = ((long long)b * HH * NN + i) * JP;
    for (int idx = tid; idx < HH * JP4; idx += 512) {
        int h = idx / JP4;
        int j4 = idx - h * JP4;
        *(float4*)&S[h * JP + j4 * 4] =
            *(const float4*)&g_dots[base + (long long)h * NN * JP + j4 * 4];
    }
    __syncthreads();

    int w = tid >> 5, lane = tid & 31;
    const int CH = JP / 32;                // 66
    float t[CH];
    float mx = -FLT_MAX;
#pragma unroll
    for (int jj = 0; jj < CH; jj++) {
        int j = jj * 32 + lane;
        float a = 0.0f;
#pragma unroll
        for (int h = 0; h < HH; h++) a += pre_s[w * HH + h] * S[h * JP + j];
        if (j >= JJ || j > i + MEMS) a = -FLT_MAX;
        t[jj] = a;
        mx = fmaxf(mx, a);
    }
#pragma unroll
    for (int o = 16; o; o >>= 1) mx = fmaxf(mx, __shfl_xor_sync(0xffffffffu, mx, o));

    float l = 0.0f;
#pragma unroll
    for (int jj = 0; jj < CH; jj++) {
        float p = __expf(t[jj] - mx);
        t[jj] = p;
        l += p;
    }
#pragma unroll
    for (int o = 16; o; o >>= 1) l += __shfl_xor_sync(0xffffffffu, l, o);
    float inv = 1.0f / l;

    __syncthreads();   // everyone done reading raw S
#pragma unroll
    for (int jj = 0; jj < CH; jj++) S[w * JP + jj * 32 + lane] = t[jj] * inv;
    __syncthreads();

#pragma unroll
    for (int jj = 0; jj < CH; jj++) {
        int j = jj * 32 + lane;
        float o_ = 0.0f;
#pragma unroll
        for (int h = 0; h < HH; h++) o_ += post_s[w * HH + h] * S[h * JP + j];
        g_dots[base + (long long)w * NN * JP + j] = o_;
    }
}

// ---------------- launch ----------------
extern "C" void kernel_launch(void* const* d_in, const int* in_sizes, int n_in,
                              void* d_out, int out_size)
{
    (void)in_sizes; (void)n_in; (void)out_size;
    const float* x       = (const float*)d_in[0];
    const float* freqs   = (const float*)d_in[1];
    const float* Wq      = (const float*)d_in[2];
    const float* Wk      = (const float*)d_in[3];
    const float* Wv      = (const float*)d_in[4];
    const float* Wo      = (const float*)d_in[5];
    const float* mem_k   = (const float*)d_in[6];
    const float* mem_v   = (const float*)d_in[7];
    const float* th_pre  = (const float*)d_in[8];
    const float* th_post = (const float*)d_in[9];
    float* out = (float*)d_out;

    float *rawq, *rawk, *rawv, *dots, *v, *o;
    cudaGetSymbolAddress((void**)&rawq, g_rawq);
    cudaGetSymbolAddress((void**)&rawk, g_rawk);
    cudaGetSymbolAddress((void**)&rawv, g_rawv);
    cudaGetSymbolAddress((void**)&dots, g_dots);
    cudaGetSymbolAddress((void**)&v, g_v);
    cudaGetSymbolAddress((void**)&o, g_o);

    cudaFuncSetAttribute(mixsoftmax_kernel,
                         cudaFuncAttributeMaxDynamicSharedMemorySize, SOFTMAX_SMEM);

    const int M = BB * NN;  // 4096

    // 1) projections
    sgemm64<<<dim3(DIM / 64, M / 64, 1), 256>>>(x, Wq, rawq, M, DIM, DIM,
                                                DIM, DIM, DIM, 0, 0, 0, 0);
    sgemm64<<<dim3(DIM / 64, M / 64, 1), 256>>>(x, Wk, rawk, M, DIM, DIM,
                                                DIM, DIM, DIM, 0, 0, 0, 0);
    sgemm64<<<dim3(DIM / 64, M / 64, 1), 256>>>(x, Wv, rawv, M, DIM, DIM,
                                                DIM, DIM, DIM, 0, 0, 0, 0);

    // 2) l2norm + rotary  (BB*NN*HH warps)
    normrot_kernel<<<(BB * NN * HH) / 8, 256>>>(freqs);

    // 3) memory slots + zero padding  (BB*HH*64 warps)
    memfill_kernel<<<(BB * HH * 64) / 8, 256>>>(mem_k, mem_v);

    // 4) dots = scale * Q K^T
    dots_kernel<<<dim3(JP / 64, NN / 64, BB * HH), 256>>>();

    // 5) mix / mask / softmax / mix (in place on g_dots)
    mixsoftmax_kernel<<<BB * NN, 512, SOFTMAX_SMEM>>>(th_pre, th_post);

    // 6) O = P @ V  (batched over b,h; C written in (b, n, h*DH) layout)
    sgemm64<<<dim3(1, NN / 64, BB * HH), 256>>>(dots, v, o, NN, DH, JP,
                                                JP, DH, DIM,
                                                (long long)NN * JP, (long long)JP * DH, 0, 1);

    // 7) final projection
    sgemm64<<<dim3(DIM / 64, M / 64, 1), 256>>>(o, Wo, out, M, DIM, DIM,
                                                DIM, DIM, DIM, 0, 0, 0, 0);
}

// round 3
// speedup vs baseline: 1.4366x; 1.4366x over previous
#include <cuda_runtime.h>
#include <cuda_bf16.h>
#include <math.h>
#include <float.h>

// ---------------- problem constants ----------------
#define BB   2
#define NN   2048
#define DIM  1024
#define HH   16
#define DH   64
#define MEMS 16
#define ROT  32
#define JJ   (NN + MEMS)   // 2064
#define JP   2112          // padded to multiple of 64
#define PADR (JP - JJ)     // 48
#define QKSCALE 10.0f

#define SOFTMAX_SMEM (HH * JP * 4)   // 135168 bytes

// ---------------- device scratch ----------------
__device__ float g_rawq[BB * NN * DIM];
__device__ float g_rawk[BB * NN * DIM];
__device__ float g_rawv[BB * NN * DIM];
__device__ float g_q[BB * HH * NN * DH];
__device__ float g_k[BB * HH * JP * DH];
__device__ float g_v[BB * HH * JP * DH];
__device__ float g_dots[BB * HH * NN * JP];   // 553 MB
__device__ float g_o[BB * NN * DIM];

// ---------------- split-bf16 helpers ----------------
__device__ __forceinline__ unsigned pack_bf2(__nv_bfloat16 a, __nv_bfloat16 b) {
    unsigned lo = __bfloat16_as_ushort(a);
    unsigned hi = __bfloat16_as_ushort(b);
    return (hi << 16) | lo;
}

__device__ __forceinline__ void split2(float x0, float x1, unsigned& h, unsigned& l) {
    __nv_bfloat16 h0 = __float2bfloat16_rn(x0);
    __nv_bfloat16 h1 = __float2bfloat16_rn(x1);
    __nv_bfloat16 l0 = __float2bfloat16_rn(x0 - __bfloat162float(h0));
    __nv_bfloat16 l1 = __float2bfloat16_rn(x1 - __bfloat162float(h1));
    h = pack_bf2(h0, h1);
    l = pack_bf2(l0, l1);
}

__device__ __forceinline__ void mma_bf16(float* d, const unsigned* a, unsigned b0, unsigned b1) {
    asm volatile(
        "mma.sync.aligned.m16n8k16.row.col.f32.bf16.bf16.f32 "
        "{%0,%1,%2,%3}, {%4,%5,%6,%7}, {%8,%9}, {%0,%1,%2,%3};\n"
        : "+f"(d[0]), "+f"(d[1]), "+f"(d[2]), "+f"(d[3])
        : "r"(a[0]), "r"(a[1]), "r"(a[2]), "r"(a[3]), "r"(b0), "r"(b1));
}

// ---------------- split-bf16 tensor-core GEMM ----------------
// C[M,N] = A[M,K] @ B ; A row-major fp32.
// BTRANS=true : B source is row-major [K][N] (proj / PV / out-proj)
// BTRANS=false: B source is [N][K] row-major, i.e. C = A @ Bsrc^T (dots)
// CMODE==1: C base per z = C + (z/HH)*NN*DIM + (z%HH)*DH (attention-output layout)
template<int BM, int BN, int WGM, int WGN, bool BTRANS, int CMODE, bool DOSCALE>
__global__ __launch_bounds__(256) void gemm_tc(
    const float* __restrict__ A, const float* __restrict__ B, float* __restrict__ C,
    int K, int lda, int ldb, int ldc,
    long long sA, long long sB, long long sC)
{
    constexpr int KS  = 26;            // smem row stride in bf16 (52 B)
    constexpr int WTM = BM / WGM, WTN = BN / WGN;
    constexpr int MT  = WTM / 16, NT  = WTN / 8;
    constexpr int ARP = BM / 64;       // float4 loads per thread for A tile
    constexpr int BRP = BN / 64;       // float4 loads per thread for B tile

    extern __shared__ char smraw[];
    __nv_bfloat16* Asm = (__nv_bfloat16*)smraw;            // [2][2][BM*KS]
    __nv_bfloat16* Bsm = Asm + 4 * BM * KS;                // [2][2][BN*KS]

    const float* Ap = A + blockIdx.z * sA;
    const float* Bp = B + blockIdx.z * sB;

    int tid = threadIdx.x, lane = tid & 31, wid = tid >> 5;
    int wm = wid / WGN, wn = wid % WGN;
    int m0 = blockIdx.y * BM, n0 = blockIdx.x * BN;
    int g = lane >> 2, c2 = (lane & 3) * 2;

    float acc[MT][NT][4];
#pragma unroll
    for (int i = 0; i < MT; i++)
#pragma unroll
        for (int j = 0; j < NT; j++)
#pragma unroll
            for (int e = 0; e < 4; e++) acc[i][j][e] = 0.0f;

    const int NK = K / 16;
    float4 ra[ARP], rb[BRP];

    // ---- global load of chunk k0 into regs ----
    auto ldgA = [&](int k0) {
#pragma unroll
        for (int i = 0; i < ARP; i++) {
            int idx = tid + i * 256;
            int r = idx >> 2, c4 = (idx & 3) << 2;
            ra[i] = *(const float4*)(Ap + (long long)(m0 + r) * lda + k0 + c4);
        }
    };
    auto ldgB = [&](int k0) {
        if (BTRANS) {
#pragma unroll
            for (int i = 0; i < BRP; i++) {
                int idx = tid + i * 256;
                int kr = idx / (BN / 4), nc4 = (idx % (BN / 4)) * 4;
                rb[i] = *(const float4*)(Bp + (long long)(k0 + kr) * ldb + n0 + nc4);
            }
        } else {
#pragma unroll
            for (int i = 0; i < BRP; i++) {
                int idx = tid + i * 256;
                int r = idx >> 2, c4 = (idx & 3) << 2;
                rb[i] = *(const float4*)(Bp + (long long)(n0 + r) * ldb + k0 + c4);
            }
        }
    };
    // ---- split + store regs -> smem buf ----
    auto stA = [&](int buf) {
        __nv_bfloat16* H = Asm + (buf * 2 + 0) * BM * KS;
        __nv_bfloat16* L = Asm + (buf * 2 + 1) * BM * KS;
#pragma unroll
        for (int i = 0; i < ARP; i++) {
            int idx = tid + i * 256;
            int r = idx >> 2, c4 = (idx & 3) << 2;
            unsigned h01, l01, h23, l23;
            split2(ra[i].x, ra[i].y, h01, l01);
            split2(ra[i].z, ra[i].w, h23, l23);
            *(unsigned*)&H[r * KS + c4]     = h01;
            *(unsigned*)&H[r * KS + c4 + 2] = h23;
            *(unsigned*)&L[r * KS + c4]     = l01;
            *(unsigned*)&L[r * KS + c4 + 2] = l23;
        }
    };
    auto stB = [&](int buf) {
        __nv_bfloat16* H = Bsm + (buf * 2 + 0) * BN * KS;
        __nv_bfloat16* L = Bsm + (buf * 2 + 1) * BN * KS;
        if (BTRANS) {
#pragma unroll
            for (int i = 0; i < BRP; i++) {
                int idx = tid + i * 256;
                int kr = idx / (BN / 4), nc4 = (idx % (BN / 4)) * 4;
                float v[4] = {rb[i].x, rb[i].y, rb[i].z, rb[i].w};
#pragma unroll
                for (int e = 0; e < 4; e++) {
                    __nv_bfloat16 h = __float2bfloat16_rn(v[e]);
                    __nv_bfloat16 l = __float2bfloat16_rn(v[e] - __bfloat162float(h));
                    H[(nc4 + e) * KS + kr] = h;
                    L[(nc4 + e) * KS + kr] = l;
                }
            }
        } else {
#pragma unroll
            for (int i = 0; i < BRP; i++) {
                int idx = tid + i * 256;
                int r = idx >> 2, c4 = (idx & 3) << 2;
                unsigned h01, l01, h23, l23;
                split2(rb[i].x, rb[i].y, h01, l01);
                split2(rb[i].z, rb[i].w, h23, l23);
                *(unsigned*)&H[r * KS + c4]     = h01;
                *(unsigned*)&H[r * KS + c4 + 2] = h23;
                *(unsigned*)&L[r * KS + c4]     = l01;
                *(unsigned*)&L[r * KS + c4 + 2] = l23;
            }
        }
    };

    auto compute = [&](int buf) {
        const __nv_bfloat16* Ah = Asm + (buf * 2 + 0) * BM * KS;
        const __nv_bfloat16* Al = Asm + (buf * 2 + 1) * BM * KS;
        const __nv_bfloat16* Bh = Bsm + (buf * 2 + 0) * BN * KS;
        const __nv_bfloat16* Bl = Bsm + (buf * 2 + 1) * BN * KS;
        unsigned afh[MT][4], afl[MT][4];
#pragma unroll
        for (int mt = 0; mt < MT; mt++) {
            int r0 = (wm * WTM + mt * 16 + g) * KS + c2;
            int r1 = (wm * WTM + mt * 16 + g + 8) * KS + c2;
            afh[mt][0] = *(const unsigned*)&Ah[r0];
            afh[mt][1] = *(const unsigned*)&Ah[r1];
            afh[mt][2] = *(const unsigned*)&Ah[r0 + 8];
            afh[mt][3] = *(const unsigned*)&Ah[r1 + 8];
            afl[mt][0] = *(const unsigned*)&Al[r0];
            afl[mt][1] = *(const unsigned*)&Al[r1];
            afl[mt][2] = *(const unsigned*)&Al[r0 + 8];
            afl[mt][3] = *(const unsigned*)&Al[r1 + 8];
        }
#pragma unroll
        for (int nt = 0; nt < NT; nt++) {
            int bi = (wn * WTN + nt * 8 + g) * KS + c2;
            unsigned bh0 = *(const unsigned*)&Bh[bi];
            unsigned bh1 = *(const unsigned*)&Bh[bi + 8];
            unsigned bl0 = *(const unsigned*)&Bl[bi];
            unsigned bl1 = *(const unsigned*)&Bl[bi + 8];
#pragma unroll
            for (int mt = 0; mt < MT; mt++) {
                mma_bf16(acc[mt][nt], afh[mt], bh0, bh1);
                mma_bf16(acc[mt][nt], afh[mt], bl0, bl1);
                mma_bf16(acc[mt][nt], afl[mt], bh0, bh1);
            }
        }
    };

    // ---- prologue ----
    ldgA(0); ldgB(0);
    stA(0);  stB(0);
    __syncthreads();

    for (int ck = 0; ck < NK; ck++) {
        int buf = ck & 1;
        bool more = (ck + 1 < NK);
        if (more) { ldgA((ck + 1) * 16); ldgB((ck + 1) * 16); }
        compute(buf);
        if (more) { stA(buf ^ 1); stB(buf ^ 1); }
        __syncthreads();
    }

    // ---- epilogue ----
    float* Cp;
    if (CMODE == 0) {
        Cp = C + blockIdx.z * sC;
    } else {
        int b = blockIdx.z / HH, h = blockIdx.z % HH;
        Cp = C + (long long)b * NN * DIM + h * DH;
    }
    const float sc = DOSCALE ? QKSCALE : 1.0f;
#pragma unroll
    for (int mt = 0; mt < MT; mt++) {
#pragma unroll
        for (int nt = 0; nt < NT; nt++) {
            int row = m0 + wm * WTM + mt * 16 + g;
            int col = n0 + wn * WTN + nt * 8 + c2;
            float2 v0 = {acc[mt][nt][0] * sc, acc[mt][nt][1] * sc};
            float2 v1 = {acc[mt][nt][2] * sc, acc[mt][nt][3] * sc};
            *(float2*)&Cp[(long long)row * ldc + col]       = v0;
            *(float2*)&Cp[(long long)(row + 8) * ldc + col] = v1;
        }
    }
}

// ---------------- l2norm + rotary for q, k, v ----------------
__global__ __launch_bounds__(256) void normrot_kernel(const float* __restrict__ freqs)
{
    int gw = (blockIdx.x * blockDim.x + threadIdx.x) >> 5;
    int lane = threadIdx.x & 31;
    int h = gw % HH;
    int n = (gw / HH) % NN;
    int b = gw / (HH * NN);

    long long rbase = ((long long)(b * NN + n)) * DIM + h * DH;
    float f = freqs[n * ROT + lane];
    float cs = cosf(f), sn = sinf(f);

    {
        float v0 = g_rawq[rbase + lane], v1 = g_rawq[rbase + 32 + lane];
        float ss = v0 * v0 + v1 * v1;
#pragma unroll
        for (int o = 16; o; o >>= 1) ss += __shfl_xor_sync(0xffffffffu, ss, o);
        float inv = 1.0f / fmaxf(sqrtf(ss), 1e-12f);
        v0 *= inv; v1 *= inv;
        float partner = __shfl_xor_sync(0xffffffffu, v0, 16);
        float rot = (lane < 16) ? -partner : partner;
        v0 = v0 * cs + rot * sn;
        long long ob = ((long long)((b * HH + h) * NN + n)) * DH;
        g_q[ob + lane] = v0;
        g_q[ob + 32 + lane] = v1;
    }
    {
        float v0 = g_rawk[rbase + lane], v1 = g_rawk[rbase + 32 + lane];
        float ss = v0 * v0 + v1 * v1;
#pragma unroll
        for (int o = 16; o; o >>= 1) ss += __shfl_xor_sync(0xffffffffu, ss, o);
        float inv = 1.0f / fmaxf(sqrtf(ss), 1e-12f);
        v0 *= inv; v1 *= inv;
        float partner = __shfl_xor_sync(0xffffffffu, v0, 16);
        float rot = (lane < 16) ? -partner : partner;
        v0 = v0 * cs + rot * sn;
        long long ob = ((long long)((b * HH + h) * JP + (MEMS + n))) * DH;
        g_k[ob + lane] = v0;
        g_k[ob + 32 + lane] = v1;
    }
    {
        float v0 = g_rawv[rbase + lane], v1 = g_rawv[rbase + 32 + lane];
        float partner = __shfl_xor_sync(0xffffffffu, v0, 16);
        float rot = (lane < 16) ? -partner : partner;
        v0 = v0 * cs + rot * sn;
        long long ob = ((long long)((b * HH + h) * JP + (MEMS + n))) * DH;
        g_v[ob + lane] = v0;
        g_v[ob + 32 + lane] = v1;
    }
}

// ---------------- memory slots + zero padding rows ----------------
__global__ __launch_bounds__(256) void memfill_kernel(
    const float* __restrict__ mem_k, const float* __restrict__ mem_v)
{
    int gw = (blockIdx.x * blockDim.x + threadIdx.x) >> 5;
    int lane = threadIdx.x & 31;
    const int RPW = MEMS + PADR;  // 64
    int r = gw % RPW;
    int h = (gw / RPW) % HH;
    int b = gw / (RPW * HH);

    if (r < MEMS) {
        long long ib = ((long long)(h * MEMS + r)) * DH;
        float k0 = mem_k[ib + lane], k1 = mem_k[ib + 32 + lane];
        float ss = k0 * k0 + k1 * k1;
#pragma unroll
        for (int o = 16; o; o >>= 1) ss += __shfl_xor_sync(0xffffffffu, ss, o);
        float inv = 1.0f / fmaxf(sqrtf(ss), 1e-12f);
        long long ob = ((long long)((b * HH + h) * JP + r)) * DH;
        g_k[ob + lane] = k0 * inv;
        g_k[ob + 32 + lane] = k1 * inv;
        g_v[ob + lane] = mem_v[ib + lane];
        g_v[ob + 32 + lane] = mem_v[ib + 32 + lane];
    } else {
        int rr = JJ + (r - MEMS);
        long long ob = ((long long)((b * HH + h) * JP + rr)) * DH;
        g_k[ob + lane] = 0.0f; g_k[ob + 32 + lane] = 0.0f;
        g_v[ob + lane] = 0.0f; g_v[ob + 32 + lane] = 0.0f;
    }
}

// ---------------- th_pre mix -> mask -> softmax -> th_post mix (in place) ----------------
__global__ __launch_bounds__(512, 1) void mixsoftmax_kernel(
    const float* __restrict__ th_pre, const float* __restrict__ th_post)
{
    extern __shared__ float S[];           // [HH][JP]
    __shared__ float pre_s[HH * HH];
    __shared__ float post_s[HH * HH];

    int tid = threadIdx.x;
    int bi = blockIdx.x;
    int b = bi / NN, i = bi % NN;

    if (tid < 256) pre_s[tid] = th_pre[tid];
    else post_s[tid - 256] = th_post[tid - 256];

    const int JP4 = JP / 4;                // 528
    long long base = ((long long)b * HH * NN + i) * JP;
    for (int idx = tid; idx < HH * JP4; idx += 512) {
        int h = idx / JP4;
        int j4 = idx - h * JP4;
        *(float4*)&S[h * JP + j4 * 4] =
            *(const float4*)&g_dots[base + (long long)h * NN * JP + j4 * 4];
    }
    __syncthreads();

    int w = tid >> 5, lane = tid & 31;
    const int CH = JP / 32;                // 66
    float t[CH];
    float mx = -FLT_MAX;
#pragma unroll
    for (int jj = 0; jj < CH; jj++) {
        int j = jj * 32 + lane;
        float a = 0.0f;
#pragma unroll
        for (int h = 0; h < HH; h++) a += pre_s[w * HH + h] * S[h * JP + j];
        if (j >= JJ || j > i + MEMS) a = -FLT_MAX;
        t[jj] = a;
        mx = fmaxf(mx, a);
    }
#pragma unroll
    for (int o = 16; o; o >>= 1) mx = fmaxf(mx, __shfl_xor_sync(0xffffffffu, mx, o));

    float l = 0.0f;
#pragma unroll
    for (int jj = 0; jj < CH; jj++) {
        float p = __expf(t[jj] - mx);
        t[jj] = p;
        l += p;
    }
#pragma unroll
    for (int o = 16; o; o >>= 1) l += __shfl_xor_sync(0xffffffffu, l, o);
    float inv = 1.0f / l;

    __syncthreads();
#pragma unroll
    for (int jj = 0; jj < CH; jj++) S[w * JP + jj * 32 + lane] = t[jj] * inv;
    __syncthreads();

#pragma unroll
    for (int jj = 0; jj < CH; jj++) {
        int j = jj * 32 + lane;
        float o_ = 0.0f;
#pragma unroll
        for (int h = 0; h < HH; h++) o_ += post_s[w * HH + h] * S[h * JP + j];
        g_dots[base + (long long)w * NN * JP + j] = o_;
    }
}

// ---------------- launch ----------------
extern "C" void kernel_launch(void* const* d_in, const int* in_sizes, int n_in,
                              void* d_out, int out_size)
{
    (void)in_sizes; (void)n_in; (void)out_size;
    const float* x       = (const float*)d_in[0];
    const float* freqs   = (const float*)d_in[1];
    const float* Wq      = (const float*)d_in[2];
    const float* Wk      = (const float*)d_in[3];
    const float* Wv      = (const float*)d_in[4];
    const float* Wo      = (const float*)d_in[5];
    const float* mem_k   = (const float*)d_in[6];
    const float* mem_v   = (const float*)d_in[7];
    const float* th_pre  = (const float*)d_in[8];
    const float* th_post = (const float*)d_in[9];
    float* out = (float*)d_out;

    float *rawq, *rawk, *rawv, *dots, *q, *k, *v, *o;
    cudaGetSymbolAddress((void**)&rawq, g_rawq);
    cudaGetSymbolAddress((void**)&rawk, g_rawk);
    cudaGetSymbolAddress((void**)&rawv, g_rawv);
    cudaGetSymbolAddress((void**)&dots, g_dots);
    cudaGetSymbolAddress((void**)&q, g_q);
    cudaGetSymbolAddress((void**)&k, g_k);
    cudaGetSymbolAddress((void**)&v, g_v);
    cudaGetSymbolAddress((void**)&o, g_o);

    cudaFuncSetAttribute(mixsoftmax_kernel,
                         cudaFuncAttributeMaxDynamicSharedMemorySize, SOFTMAX_SMEM);

    // GEMM configs
    // proj/out: BM=128 BN=128 WGM=2 WGN=4, BTRANS
    auto kproj = gemm_tc<128, 128, 2, 4, true, 0, false>;
    // dots: BM=128 BN=64 WGM=4 WGN=2, B = K rows (no trans), scale
    auto kdots = gemm_tc<128, 64, 4, 2, false, 0, true>;
    // PV: BM=128 BN=64 WGM=4 WGN=2, BTRANS, cmode=1
    auto kpv = gemm_tc<128, 64, 4, 2, true, 1, false>;

    const int SM_BIG = (128 + 128) * 26 * 2 * 2 * 2;   // 53248
    const int SM_SML = (128 + 64)  * 26 * 2 * 2 * 2;   // 39936
    cudaFuncSetAttribute(kproj, cudaFuncAttributeMaxDynamicSharedMemorySize, SM_BIG);
    cudaFuncSetAttribute(kdots, cudaFuncAttributeMaxDynamicSharedMemorySize, SM_SML);
    cudaFuncSetAttribute(kpv,   cudaFuncAttributeMaxDynamicSharedMemorySize, SM_SML);

    const int M = BB * NN;  // 4096

    // 1) projections: C = x @ W
    kproj<<<dim3(DIM / 128, M / 128, 1), 256, SM_BIG>>>(x, Wq, rawq, DIM, DIM, DIM, DIM, 0, 0, 0);
    kproj<<<dim3(DIM / 128, M / 128, 1), 256, SM_BIG>>>(x, Wk, rawk, DIM, DIM, DIM, DIM, 0, 0, 0);
    kproj<<<dim3(DIM / 128, M / 128, 1), 256, SM_BIG>>>(x, Wv, rawv, DIM, DIM, DIM, DIM, 0, 0, 0);

    // 2) l2norm + rotary
    normrot_kernel<<<(BB * NN * HH) / 8, 256>>>(freqs);

    // 3) memory slots + padding
    memfill_kernel<<<(BB * HH * 64) / 8, 256>>>(mem_k, mem_v);

    // 4) dots = scale * Q @ K^T   (batched over b,h)
    kdots<<<dim3(JP / 64, NN / 128, BB * HH), 256, SM_SML>>>(
        q, k, dots, DH, DH, DH, JP,
        (long long)NN * DH, (long long)JP * DH, (long long)NN * JP);

    // 5) mix / mask / softmax / mix (in place)
    mixsoftmax_kernel<<<BB * NN, 512, SOFTMAX_SMEM>>>(th_pre, th_post);

    // 6) O = P @ V   (batched over b,h; output in (b,n,h*DH) layout)
    kpv<<<dim3(1, NN / 128, BB * HH), 256, SM_SML>>>(
        dots, v, o, JP, JP, DH, DIM,
        (long long)NN * JP, (long long)JP * DH, 0);

    // 7) final projection
    kproj<<<dim3(DIM / 128, M / 128, 1), 256, SM_BIG>>>(o, Wo, out, DIM, DIM, DIM, DIM, 0, 0, 0);
}

// round 4
// speedup vs baseline: 1.4396x; 1.0021x over previous
#include <cuda_runtime.h>
#include <cuda_bf16.h>
#include <math.h>
#include <float.h>

// ---------------- problem constants ----------------
#define BB   2
#define NN   2048
#define DIM  1024
#define HH   16
#define DH   64
#define MEMS 16
#define ROT  32
#define JJ   (NN + MEMS)   // 2064
#define JP   2112          // padded to multiple of 64
#define PADR (JP - JJ)     // 48
#define QKSCALE 10.0f

#define SOFTMAX_SMEM (HH * JP * 4)   // 135168 bytes

// ---------------- device scratch ----------------
__device__ float g_rawq[BB * NN * DIM];
__device__ float g_rawk[BB * NN * DIM];
__device__ float g_rawv[BB * NN * DIM];
__device__ float g_q[BB * HH * NN * DH];
__device__ float g_k[BB * HH * JP * DH];
__device__ float g_v[BB * HH * JP * DH];
__device__ float g_dots[BB * HH * NN * JP];   // 553 MB
__device__ float g_o[BB * NN * DIM];

// ---------------- split-bf16 helpers ----------------
__device__ __forceinline__ unsigned pack_bf2(__nv_bfloat16 a, __nv_bfloat16 b) {
    unsigned lo = __bfloat16_as_ushort(a);
    unsigned hi = __bfloat16_as_ushort(b);
    return (hi << 16) | lo;
}

__device__ __forceinline__ void split2(float x0, float x1, unsigned& h, unsigned& l) {
    __nv_bfloat16 h0 = __float2bfloat16_rn(x0);
    __nv_bfloat16 h1 = __float2bfloat16_rn(x1);
    __nv_bfloat16 l0 = __float2bfloat16_rn(x0 - __bfloat162float(h0));
    __nv_bfloat16 l1 = __float2bfloat16_rn(x1 - __bfloat162float(h1));
    h = pack_bf2(h0, h1);
    l = pack_bf2(l0, l1);
}

__device__ __forceinline__ void mma_bf16(float* d, const unsigned* a, unsigned b0, unsigned b1) {
    asm volatile(
        "mma.sync.aligned.m16n8k16.row.col.f32.bf16.bf16.f32 "
        "{%0,%1,%2,%3}, {%4,%5,%6,%7}, {%8,%9}, {%0,%1,%2,%3};\n"
        : "+f"(d[0]), "+f"(d[1]), "+f"(d[2]), "+f"(d[3])
        : "r"(a[0]), "r"(a[1]), "r"(a[2]), "r"(a[3]), "r"(b0), "r"(b1));
}

// ---------------- split-bf16 tensor-core GEMM ----------------
// C[M,N] = A[M,K] @ B ; A row-major fp32.
// BTRANS=true : B source is row-major [K][N] (proj / PV / out-proj)
// BTRANS=false: B source is [N][K] row-major, i.e. C = A @ Bsrc^T (dots)
// CMODE==1: C base per z = C + (z/HH)*NN*DIM + (z%HH)*DH (attention-output layout)
template<int BM, int BN, int WGM, int WGN, bool BTRANS, int CMODE, bool DOSCALE>
__global__ __launch_bounds__(256) void gemm_tc(
    const float* __restrict__ A, const float* __restrict__ B, float* __restrict__ C,
    int K, int lda, int ldb, int ldc,
    long long sA, long long sB, long long sC)
{
    constexpr int KS  = 26;            // smem row stride in bf16 (52 B)
    constexpr int WTM = BM / WGM, WTN = BN / WGN;
    constexpr int MT  = WTM / 16, NT  = WTN / 8;
    constexpr int ARP = BM / 64;       // float4 loads per thread for A tile
    constexpr int BRP = BN / 64;       // float4 loads per thread for B tile

    extern __shared__ char smraw[];
    __nv_bfloat16* Asm = (__nv_bfloat16*)smraw;            // [2][2][BM*KS]
    __nv_bfloat16* Bsm = Asm + 4 * BM * KS;                // [2][2][BN*KS]

    const float* Ap = A + blockIdx.z * sA;
    const float* Bp = B + blockIdx.z * sB;

    int tid = threadIdx.x, lane = tid & 31, wid = tid >> 5;
    int wm = wid / WGN, wn = wid % WGN;
    int m0 = blockIdx.y * BM, n0 = blockIdx.x * BN;
    int g = lane >> 2, c2 = (lane & 3) * 2;

    float acc[MT][NT][4];
#pragma unroll
    for (int i = 0; i < MT; i++)
#pragma unroll
        for (int j = 0; j < NT; j++)
#pragma unroll
            for (int e = 0; e < 4; e++) acc[i][j][e] = 0.0f;

    const int NK = K / 16;
    float4 ra[ARP], rb[BRP];

    // ---- global load of chunk k0 into regs ----
    auto ldgA = [&](int k0) {
#pragma unroll
        for (int i = 0; i < ARP; i++) {
            int idx = tid + i * 256;
            int r = idx >> 2, c4 = (idx & 3) << 2;
            ra[i] = *(const float4*)(Ap + (long long)(m0 + r) * lda + k0 + c4);
        }
    };
    auto ldgB = [&](int k0) {
        if (BTRANS) {
#pragma unroll
            for (int i = 0; i < BRP; i++) {
                int idx = tid + i * 256;
                int kr = idx / (BN / 4), nc4 = (idx % (BN / 4)) * 4;
                rb[i] = *(const float4*)(Bp + (long long)(k0 + kr) * ldb + n0 + nc4);
            }
        } else {
#pragma unroll
            for (int i = 0; i < BRP; i++) {
                int idx = tid + i * 256;
                int r = idx >> 2, c4 = (idx & 3) << 2;
                rb[i] = *(const float4*)(Bp + (long long)(n0 + r) * ldb + k0 + c4);
            }
        }
    };
    // ---- split + store regs -> smem buf ----
    auto stA = [&](int buf) {
        __nv_bfloat16* H = Asm + (buf * 2 + 0) * BM * KS;
        __nv_bfloat16* L = Asm + (buf * 2 + 1) * BM * KS;
#pragma unroll
        for (int i = 0; i < ARP; i++) {
            int idx = tid + i * 256;
            int r = idx >> 2, c4 = (idx & 3) << 2;
            unsigned h01, l01, h23, l23;
            split2(ra[i].x, ra[i].y, h01, l01);
            split2(ra[i].z, ra[i].w, h23, l23);
            *(unsigned*)&H[r * KS + c4]     = h01;
            *(unsigned*)&H[r * KS + c4 + 2] = h23;
            *(unsigned*)&L[r * KS + c4]     = l01;
            *(unsigned*)&L[r * KS + c4 + 2] = l23;
        }
    };
    auto stB = [&](int buf) {
        __nv_bfloat16* H = Bsm + (buf * 2 + 0) * BN * KS;
        __nv_bfloat16* L = Bsm + (buf * 2 + 1) * BN * KS;
        if (BTRANS) {
#pragma unroll
            for (int i = 0; i < BRP; i++) {
                int idx = tid + i * 256;
                int kr = idx / (BN / 4), nc4 = (idx % (BN / 4)) * 4;
                float v[4] = {rb[i].x, rb[i].y, rb[i].z, rb[i].w};
#pragma unroll
                for (int e = 0; e < 4; e++) {
                    __nv_bfloat16 h = __float2bfloat16_rn(v[e]);
                    __nv_bfloat16 l = __float2bfloat16_rn(v[e] - __bfloat162float(h));
                    H[(nc4 + e) * KS + kr] = h;
                    L[(nc4 + e) * KS + kr] = l;
                }
            }
        } else {
#pragma unroll
            for (int i = 0; i < BRP; i++) {
                int idx = tid + i * 256;
                int r = idx >> 2, c4 = (idx & 3) << 2;
                unsigned h01, l01, h23, l23;
                split2(rb[i].x, rb[i].y, h01, l01);
                split2(rb[i].z, rb[i].w, h23, l23);
                *(unsigned*)&H[r * KS + c4]     = h01;
                *(unsigned*)&H[r * KS + c4 + 2] = h23;
                *(unsigned*)&L[r * KS + c4]     = l01;
                *(unsigned*)&L[r * KS + c4 + 2] = l23;
            }
        }
    };

    auto compute = [&](int buf) {
        const __nv_bfloat16* Ah = Asm + (buf * 2 + 0) * BM * KS;
        const __nv_bfloat16* Al = Asm + (buf * 2 + 1) * BM * KS;
        const __nv_bfloat16* Bh = Bsm + (buf * 2 + 0) * BN * KS;
        const __nv_bfloat16* Bl = Bsm + (buf * 2 + 1) * BN * KS;
        unsigned afh[MT][4], afl[MT][4];
#pragma unroll
        for (int mt = 0; mt < MT; mt++) {
            int r0 = (wm * WTM + mt * 16 + g) * KS + c2;
            int r1 = (wm * WTM + mt * 16 + g + 8) * KS + c2;
            afh[mt][0] = *(const unsigned*)&Ah[r0];
            afh[mt][1] = *(const unsigned*)&Ah[r1];
            afh[mt][2] = *(const unsigned*)&Ah[r0 + 8];
            afh[mt][3] = *(const unsigned*)&Ah[r1 + 8];
            afl[mt][0] = *(const unsigned*)&Al[r0];
            afl[mt][1] = *(const unsigned*)&Al[r1];
            afl[mt][2] = *(const unsigned*)&Al[r0 + 8];
            afl[mt][3] = *(const unsigned*)&Al[r1 + 8];
        }
#pragma unroll
        for (int nt = 0; nt < NT; nt++) {
            int bi = (wn * WTN + nt * 8 + g) * KS + c2;
            unsigned bh0 = *(const unsigned*)&Bh[bi];
            unsigned bh1 = *(const unsigned*)&Bh[bi + 8];
            unsigned bl0 = *(const unsigned*)&Bl[bi];
            unsigned bl1 = *(const unsigned*)&Bl[bi + 8];
#pragma unroll
            for (int mt = 0; mt < MT; mt++) {
                mma_bf16(acc[mt][nt], afh[mt], bh0, bh1);
                mma_bf16(acc[mt][nt], afh[mt], bl0, bl1);
                mma_bf16(acc[mt][nt], afl[mt], bh0, bh1);
            }
        }
    };

    // ---- prologue ----
    ldgA(0); ldgB(0);
    stA(0);  stB(0);
    __syncthreads();

    for (int ck = 0; ck < NK; ck++) {
        int buf = ck & 1;
        bool more = (ck + 1 < NK);
        if (more) { ldgA((ck + 1) * 16); ldgB((ck + 1) * 16); }
        compute(buf);
        if (more) { stA(buf ^ 1); stB(buf ^ 1); }
        __syncthreads();
    }

    // ---- epilogue ----
    float* Cp;
    if (CMODE == 0) {
        Cp = C + blockIdx.z * sC;
    } else {
        int b = blockIdx.z / HH, h = blockIdx.z % HH;
        Cp = C + (long long)b * NN * DIM + h * DH;
    }
    const float sc = DOSCALE ? QKSCALE : 1.0f;
#pragma unroll
    for (int mt = 0; mt < MT; mt++) {
#pragma unroll
        for (int nt = 0; nt < NT; nt++) {
            int row = m0 + wm * WTM + mt * 16 + g;
            int col = n0 + wn * WTN + nt * 8 + c2;
            float2 v0 = {acc[mt][nt][0] * sc, acc[mt][nt][1] * sc};
            float2 v1 = {acc[mt][nt][2] * sc, acc[mt][nt][3] * sc};
            *(float2*)&Cp[(long long)row * ldc + col]       = v0;
            *(float2*)&Cp[(long long)(row + 8) * ldc + col] = v1;
        }
    }
}

// ---------------- l2norm + rotary for q, k, v ----------------
__global__ __launch_bounds__(256) void normrot_kernel(const float* __restrict__ freqs)
{
    int gw = (blockIdx.x * blockDim.x + threadIdx.x) >> 5;
    int lane = threadIdx.x & 31;
    int h = gw % HH;
    int n = (gw / HH) % NN;
    int b = gw / (HH * NN);

    long long rbase = ((long long)(b * NN + n)) * DIM + h * DH;
    float f = freqs[n * ROT + lane];
    float cs = cosf(f), sn = sinf(f);

    {
        float v0 = g_rawq[rbase + lane], v1 = g_rawq[rbase + 32 + lane];
        float ss = v0 * v0 + v1 * v1;
#pragma unroll
        for (int o = 16; o; o >>= 1) ss += __shfl_xor_sync(0xffffffffu, ss, o);
        float inv = 1.0f / fmaxf(sqrtf(ss), 1e-12f);
        v0 *= inv; v1 *= inv;
        float partner = __shfl_xor_sync(0xffffffffu, v0, 16);
        float rot = (lane < 16) ? -partner : partner;
        v0 = v0 * cs + rot * sn;
        long long ob = ((long long)((b * HH + h) * NN + n)) * DH;
        g_q[ob + lane] = v0;
        g_q[ob + 32 + lane] = v1;
    }
    {
        float v0 = g_rawk[rbase + lane], v1 = g_rawk[rbase + 32 + lane];
        float ss = v0 * v0 + v1 * v1;
#pragma unroll
        for (int o = 16; o; o >>= 1) ss += __shfl_xor_sync(0xffffffffu, ss, o);
        float inv = 1.0f / fmaxf(sqrtf(ss), 1e-12f);
        v0 *= inv; v1 *= inv;
        float partner = __shfl_xor_sync(0xffffffffu, v0, 16);
        float rot = (lane < 16) ? -partner : partner;
        v0 = v0 * cs + rot * sn;
        long long ob = ((long long)((b * HH + h) * JP + (MEMS + n))) * DH;
        g_k[ob + lane] = v0;
        g_k[ob + 32 + lane] = v1;
    }
    {
        float v0 = g_rawv[rbase + lane], v1 = g_rawv[rbase + 32 + lane];
        float partner = __shfl_xor_sync(0xffffffffu, v0, 16);
        float rot = (lane < 16) ? -partner : partner;
        v0 = v0 * cs + rot * sn;
        long long ob = ((long long)((b * HH + h) * JP + (MEMS + n))) * DH;
        g_v[ob + lane] = v0;
        g_v[ob + 32 + lane] = v1;
    }
}

// ---------------- memory slots + zero padding rows ----------------
__global__ __launch_bounds__(256) void memfill_kernel(
    const float* __restrict__ mem_k, const float* __restrict__ mem_v)
{
    int gw = (blockIdx.x * blockDim.x + threadIdx.x) >> 5;
    int lane = threadIdx.x & 31;
    const int RPW = MEMS + PADR;  // 64
    int r = gw % RPW;
    int h = (gw / RPW) % HH;
    int b = gw / (RPW * HH);

    if (r < MEMS) {
        long long ib = ((long long)(h * MEMS + r)) * DH;
        float k0 = mem_k[ib + lane], k1 = mem_k[ib + 32 + lane];
        float ss = k0 * k0 + k1 * k1;
#pragma unroll
        for (int o = 16; o; o >>= 1) ss += __shfl_xor_sync(0xffffffffu, ss, o);
        float inv = 1.0f / fmaxf(sqrtf(ss), 1e-12f);
        long long ob = ((long long)((b * HH + h) * JP + r)) * DH;
        g_k[ob + lane] = k0 * inv;
        g_k[ob + 32 + lane] = k1 * inv;
        g_v[ob + lane] = mem_v[ib + lane];
        g_v[ob + 32 + lane] = mem_v[ib + 32 + lane];
    } else {
        int rr = JJ + (r - MEMS);
        long long ob = ((long long)((b * HH + h) * JP + rr)) * DH;
        g_k[ob + lane] = 0.0f; g_k[ob + 32 + lane] = 0.0f;
        g_v[ob + lane] = 0.0f; g_v[ob + 32 + lane] = 0.0f;
    }
}

// ---------------- th_pre mix -> mask -> softmax -> th_post mix (in place) ----------------
__global__ __launch_bounds__(512, 1) void mixsoftmax_kernel(
    const float* __restrict__ th_pre, const float* __restrict__ th_post)
{
    extern __shared__ float S[];           // [HH][JP]
    __shared__ float pre_s[HH * HH];
    __shared__ float post_s[HH * HH];

    int tid = threadIdx.x;
    int bi = blockIdx.x;
    int b = bi / NN, i = bi % NN;

    if (tid < 256) pre_s[tid] = th_pre[tid];
    else post_s[tid - 256] = th_post[tid - 256];

    const int JP4 = JP / 4;                // 528
    long long base = ((long long)b * HH * NN + i) * JP;
    for (int idx = tid; idx < HH * JP4; idx += 512) {
        int h = idx / JP4;
        int j4 = idx - h * JP4;
        *(float4*)&S[h * JP + j4 * 4] =
            *(const float4*)&g_dots[base + (long long)h * NN * JP + j4 * 4];
    }
    __syncthreads();

    int w = tid >> 5, lane = tid & 31;
    const int CH = JP / 32;                // 66
    float t[CH];
    float mx = -FLT_MAX;
#pragma unroll
    for (int jj = 0; jj < CH; jj++) {
        int j = jj * 32 + lane;
        float a = 0.0f;
#pragma unroll
        for (int h = 0; h < HH; h++) a += pre_s[w * HH + h] * S[h * JP + j];
        if (j >= JJ || j > i + MEMS) a = -FLT_MAX;
        t[jj] = a;
        mx = fmaxf(mx, a);
    }
#pragma unroll
    for (int o = 16; o; o >>= 1) mx = fmaxf(mx, __shfl_xor_sync(0xffffffffu, mx, o));

    float l = 0.0f;
#pragma unroll
    for (int jj = 0; jj < CH; jj++) {
        float p = __expf(t[jj] - mx);
        t[jj] = p;
        l += p;
    }
#pragma unroll
    for (int o = 16; o; o >>= 1) l += __shfl_xor_sync(0xffffffffu, l, o);
    float inv = 1.0f / l;

    __syncthreads();
#pragma unroll
    for (int jj = 0; jj < CH; jj++) S[w * JP + jj * 32 + lane] = t[jj] * inv;
    __syncthreads();

#pragma unroll
    for (int jj = 0; jj < CH; jj++) {
        int j = jj * 32 + lane;
        float o_ = 0.0f;
#pragma unroll
        for (int h = 0; h < HH; h++) o_ += post_s[w * HH + h] * S[h * JP + j];
        g_dots[base + (long long)w * NN * JP + j] = o_;
    }
}

// ---------------- launch ----------------
extern "C" void kernel_launch(void* const* d_in, const int* in_sizes, int n_in,
                              void* d_out, int out_size)
{
    (void)in_sizes; (void)n_in; (void)out_size;
    const float* x       = (const float*)d_in[0];
    const float* freqs   = (const float*)d_in[1];
    const float* Wq      = (const float*)d_in[2];
    const float* Wk      = (const float*)d_in[3];
    const float* Wv      = (const float*)d_in[4];
    const float* Wo      = (const float*)d_in[5];
    const float* mem_k   = (const float*)d_in[6];
    const float* mem_v   = (const float*)d_in[7];
    const float* th_pre  = (const float*)d_in[8];
    const float* th_post = (const float*)d_in[9];
    float* out = (float*)d_out;

    float *rawq, *rawk, *rawv, *dots, *q, *k, *v, *o;
    cudaGetSymbolAddress((void**)&rawq, g_rawq);
    cudaGetSymbolAddress((void**)&rawk, g_rawk);
    cudaGetSymbolAddress((void**)&rawv, g_rawv);
    cudaGetSymbolAddress((void**)&dots, g_dots);
    cudaGetSymbolAddress((void**)&q, g_q);
    cudaGetSymbolAddress((void**)&k, g_k);
    cudaGetSymbolAddress((void**)&v, g_v);
    cudaGetSymbolAddress((void**)&o, g_o);

    cudaFuncSetAttribute(mixsoftmax_kernel,
                         cudaFuncAttributeMaxDynamicSharedMemorySize, SOFTMAX_SMEM);

    // GEMM configs
    // proj/out: BM=128 BN=128 WGM=2 WGN=4, BTRANS
    auto kproj = gemm_tc<128, 128, 2, 4, true, 0, false>;
    // dots: BM=128 BN=64 WGM=4 WGN=2, B = K rows (no trans), scale
    auto kdots = gemm_tc<128, 64, 4, 2, false, 0, true>;
    // PV: BM=128 BN=64 WGM=4 WGN=2, BTRANS, cmode=1
    auto kpv = gemm_tc<128, 64, 4, 2, true, 1, false>;

    const int SM_BIG = (128 + 128) * 26 * 2 * 2 * 2;   // 53248
    const int SM_SML = (128 + 64)  * 26 * 2 * 2 * 2;   // 39936
    cudaFuncSetAttribute(kproj, cudaFuncAttributeMaxDynamicSharedMemorySize, SM_BIG);
    cudaFuncSetAttribute(kdots, cudaFuncAttributeMaxDynamicSharedMemorySize, SM_SML);
    cudaFuncSetAttribute(kpv,   cudaFuncAttributeMaxDynamicSharedMemorySize, SM_SML);

    const int M = BB * NN;  // 4096

    // 1) projections: C = x @ W
    kproj<<<dim3(DIM / 128, M / 128, 1), 256, SM_BIG>>>(x, Wq, rawq, DIM, DIM, DIM, DIM, 0, 0, 0);
    kproj<<<dim3(DIM / 128, M / 128, 1), 256, SM_BIG>>>(x, Wk, rawk, DIM, DIM, DIM, DIM, 0, 0, 0);
    kproj<<<dim3(DIM / 128, M / 128, 1), 256, SM_BIG>>>(x, Wv, rawv, DIM, DIM, DIM, DIM, 0, 0, 0);

    // 2) l2norm + rotary
    normrot_kernel<<<(BB * NN * HH) / 8, 256>>>(freqs);

    // 3) memory slots + padding
    memfill_kernel<<<(BB * HH * 64) / 8, 256>>>(mem_k, mem_v);

    // 4) dots = scale * Q @ K^T   (batched over b,h)
    kdots<<<dim3(JP / 64, NN / 128, BB * HH), 256, SM_SML>>>(
        q, k, dots, DH, DH, DH, JP,
        (long long)NN * DH, (long long)JP * DH, (long long)NN * JP);

    // 5) mix / mask / softmax / mix (in place)
    mixsoftmax_kernel<<<BB * NN, 512, SOFTMAX_SMEM>>>(th_pre, th_post);

    // 6) O = P @ V   (batched over b,h; output in (b,n,h*DH) layout)
    kpv<<<dim3(1, NN / 128, BB * HH), 256, SM_SML>>>(
        dots, v, o, JP, JP, DH, DIM,
        (long long)NN * JP, (long long)JP * DH, 0);

    // 7) final projection
    kproj<<<dim3(DIM / 128, M / 128, 1), 256, SM_BIG>>>(o, Wo, out, DIM, DIM, DIM, DIM, 0, 0, 0);
}